// round 10
// baseline (speedup 1.0000x reference)
#include <cuda_runtime.h>
#include <cuda_fp16.h>
#include <cstdint>

// GhostLinearTandem, two-pass (tcgen05 rejected by harness ptxas @ sm_103):
//  pass 1 (ghost_dequant): W fp16 -> 64MiB scratch (LUT fp16 in smem), x -> fp16.
//  pass 2 (ghost_gemm): warp-specialized fp16 mma.sync GEMM.
//    BM=128 BN=256 BK=64, grid (4,32)=128 CTAs -> 1 CTA/SM, SINGLE WAVE.
//    320 threads: 8 consumer warps (64x64 warp tiles, LDSM.x4 + HMMA.16816),
//    2 producer warps (all cp.async). mbarrier full/empty ring (3 slots),
//    cp.async.mbarrier.arrive.NOINC completion signaling (without .noinc each
//    arrive also bumps the expected count and the barrier never completes ->
//    round-9 deadlock). No __syncthreads in the mainloop.

#define M_TOTAL 512
#define N_TOTAL 8192
#define K_TOTAL 4096

__device__ __align__(16) __half g_W[(size_t)N_TOTAL * K_TOTAL];   // 64 MiB
__device__ __align__(16) __half g_xh[(size_t)M_TOTAL * K_TOTAL];  // 4 MiB

__device__ __forceinline__ uint32_t smem_u32(const void* p) {
    uint32_t a;
    asm("{ .reg .u64 t; cvta.to.shared.u64 t, %1; cvt.u32.u64 %0, t; }"
        : "=r"(a) : "l"(p));
    return a;
}
#define SWZ128(off) ((off) ^ (((off) >> 3) & 0x70))

#define CP16(dst, src) \
    asm volatile("cp.async.cg.shared.global [%0], [%1], 16;" :: "r"(dst), "l"(src))
#define CP_MBAR_ARRIVE(bar) \
    asm volatile("cp.async.mbarrier.arrive.noinc.shared.b64 [%0];" :: "r"(bar) : "memory")
#define CP_WAIT_ALL() asm volatile("cp.async.wait_all;" ::: "memory")

#define MBAR_INIT(a, n) \
    asm volatile("mbarrier.init.shared.b64 [%0], %1;" :: "r"(a), "r"(n) : "memory")
#define MBAR_ARRIVE(a) \
    asm volatile("mbarrier.arrive.shared.b64 _, [%0];" :: "r"(a) : "memory")
#define MBAR_WAIT(a, par) do {                                              \
    uint32_t _m = (a), _p = (par);                                          \
    asm volatile(                                                           \
        "{\n\t.reg .pred P;\n\t"                                            \
        "W%=:\n\t"                                                          \
        "mbarrier.try_wait.parity.acquire.cta.shared::cta.b64 P, [%0], %1, 0x989680;\n\t" \
        "@P bra.uni D%=;\n\t"                                               \
        "bra.uni W%=;\n\t"                                                  \
        "D%=:\n\t}"                                                         \
        :: "r"(_m), "r"(_p) : "memory");                                    \
} while (0)

#define LDSM_X4(r0, r1, r2, r3, addr)                                     \
    asm volatile("ldmatrix.sync.aligned.m8n8.x4.shared.b16 {%0,%1,%2,%3}, [%4];" \
                 : "=r"(r0), "=r"(r1), "=r"(r2), "=r"(r3) : "r"(addr))

#define MMA_F16(d, a0, a1, a2, a3, b0, b1)                             \
    asm volatile(                                                      \
        "mma.sync.aligned.m16n8k16.row.col.f32.f16.f16.f32 "           \
        "{%0,%1,%2,%3}, {%4,%5,%6,%7}, {%8,%9}, {%0,%1,%2,%3};\n"      \
        : "+f"((d)[0]), "+f"((d)[1]), "+f"((d)[2]), "+f"((d)[3])       \
        : "r"(a0), "r"(a1), "r"(a2), "r"(a3), "r"(b0), "r"(b1))

// ---------------------------------------------------------------- pass 1
__global__ __launch_bounds__(1024)
void ghost_dequant(const int* __restrict__ base_idx,
                   const int* __restrict__ fine_idx,
                   const float* __restrict__ scale,
                   const float* __restrict__ lut,
                   const float* __restrict__ x) {
    extern __shared__ __half lut_s[];  // 65536 fp16 = 128KB
    #pragma unroll 4
    for (int i = threadIdx.x; i < 65536; i += 1024)
        lut_s[i] = __float2half_rn(lut[i]);
    __syncthreads();

    size_t t = (size_t)blockIdx.x * blockDim.x + threadIdx.x;
    size_t stride = (size_t)gridDim.x * blockDim.x;

    const float4* xp = (const float4*)x;
    for (size_t g = t; g < (size_t)M_TOTAL * K_TOTAL / 8; g += stride) {
        float4 u = xp[2 * g], v = xp[2 * g + 1];
        __half2 h[4] = {__floats2half2_rn(u.x, u.y), __floats2half2_rn(u.z, u.w),
                        __floats2half2_rn(v.x, v.y), __floats2half2_rn(v.z, v.w)};
        *(uint4*)&g_xh[g * 8] = *(uint4*)h;
    }

    const int4* bp = (const int4*)base_idx;
    const int4* fp = (const int4*)fine_idx;
    const size_t NG = (size_t)N_TOTAL * K_TOTAL / 8;
    #pragma unroll 2
    for (size_t g = t; g < NG; g += stride) {
        int row = (int)(g >> 9);
        float scl = __ldg(&scale[row]);
        int4 b0 = bp[2 * g], b1 = bp[2 * g + 1];
        int4 f0 = fp[2 * g], f1 = fp[2 * g + 1];
        __half2 h[4];
        h[0] = __floats2half2_rn(__half2float(lut_s[(b0.x << 8) + f0.x]) * scl,
                                 __half2float(lut_s[(b0.y << 8) + f0.y]) * scl);
        h[1] = __floats2half2_rn(__half2float(lut_s[(b0.z << 8) + f0.z]) * scl,
                                 __half2float(lut_s[(b0.w << 8) + f0.w]) * scl);
        h[2] = __floats2half2_rn(__half2float(lut_s[(b1.x << 8) + f1.x]) * scl,
                                 __half2float(lut_s[(b1.y << 8) + f1.y]) * scl);
        h[3] = __floats2half2_rn(__half2float(lut_s[(b1.z << 8) + f1.z]) * scl,
                                 __half2float(lut_s[(b1.w << 8) + f1.w]) * scl);
        *(uint4*)&g_W[g * 8] = *(uint4*)h;
    }
}

// ---------------------------------------------------------------- pass 2
#define BM 128
#define BN 256
#define BKH 64                       // halves per stage (128 B per row)
#define NS (K_TOTAL / BKH)           // 64 stages
#define NSLOT 3
#define A_BYTES (BM * 128)           // 16384
#define B_BYTES (BN * 128)           // 32768
#define STAGE_BYTES (A_BYTES + B_BYTES)  // 49152
#define SMEM_MB (NSLOT * STAGE_BYTES)    // 147456: full[0..2], empty[0..2]
#define SMEM_GEMM (SMEM_MB + 64)
#define THREADS 320                  // 8 consumer + 2 producer warps
#define N_CONS 256

__global__ __launch_bounds__(THREADS, 1)
void ghost_gemm(float* __restrict__ out) {
    extern __shared__ char smem[];
    const uint32_t sb = smem_u32(smem);
    const int tid = threadIdx.x;
    const int warp = tid >> 5, lane = tid & 31;
    const int m0 = blockIdx.x * BM;    // M fastest -> W L2 reuse
    const int n0 = blockIdx.y * BN;

    const uint32_t FULL = sb + SMEM_MB;        // 3 x 8B
    const uint32_t EMPTY = sb + SMEM_MB + 24;  // 3 x 8B

    if (tid == 0) {
        #pragma unroll
        for (int i = 0; i < NSLOT; i++) {
            MBAR_INIT(FULL + 8 * i, 64);    // 2 producer warps
            MBAR_INIT(EMPTY + 8 * i, N_CONS);
        }
    }
    __syncthreads();

    if (tid >= N_CONS) {
        // ---------------- producers (warps 8,9) ----------------
        const int pt = tid - N_CONS;   // 0..63
        const __half* Ag = g_xh + (size_t)m0 * K_TOTAL;
        const __half* Bg = g_W + (size_t)n0 * K_TOTAL;
        int slot = 0, phase = 1;       // empty-wait passes for first ring fill
        for (int s = 0; s < NS; ++s) {
            MBAR_WAIT(EMPTY + 8 * slot, phase);
            const int kh = s * BKH;
            const uint32_t base = sb + slot * STAGE_BYTES;
            #pragma unroll
            for (int i = 0; i < 48; i++) {
                int c = pt + i * 64;                 // 0..3071
                if (c < 1024) {                      // A chunk
                    int row = c >> 3, ci = c & 7;
                    CP16(base + SWZ128(row * 128 + ci * 16),
                         Ag + (size_t)row * K_TOTAL + kh + ci * 8);
                } else {                             // B chunk
                    int cb = c - 1024, row = cb >> 3, ci = cb & 7;
                    CP16(base + A_BYTES + SWZ128(row * 128 + ci * 16),
                         Bg + (size_t)row * K_TOTAL + kh + ci * 8);
                }
            }
            CP_MBAR_ARRIVE(FULL + 8 * slot);
            if (++slot == NSLOT) { slot = 0; phase ^= 1; }
        }
        CP_WAIT_ALL();
        return;
    }

    // ---------------- consumers (warps 0..7): 2 x 4 grid of 64x64 tiles ----
    const int warp_m = warp & 1;
    const int warp_n = warp >> 1;

    const int a_row0 = warp_m * 64 + ((lane >> 3) & 1) * 8 + (lane & 7);
    const int a_koff = (lane >> 4) * 8;
    const int b_row0 = warp_n * 64 + ((lane >> 4) & 1) * 8 + (lane & 7);
    const int b_koff = ((lane >> 3) & 1) * 8;
    uint32_t a_rowoff[4], b_rowoff[4];
    #pragma unroll
    for (int i = 0; i < 4; i++) {
        a_rowoff[i] = (a_row0 + i * 16) * 128 + a_koff * 2;
        b_rowoff[i] = (b_row0 + i * 16) * 128 + b_koff * 2;
    }

    float acc[4][8][4];
    #pragma unroll
    for (int mt = 0; mt < 4; mt++)
        #pragma unroll
        for (int nt = 0; nt < 8; nt++)
            #pragma unroll
            for (int r = 0; r < 4; r++) acc[mt][nt][r] = 0.0f;

    int slot = 0, phase = 0;
    for (int s = 0; s < NS; ++s) {
        MBAR_WAIT(FULL + 8 * slot, phase);
        const uint32_t Abase = sb + slot * STAGE_BYTES;
        const uint32_t Bbase = Abase + A_BYTES;

        #pragma unroll
        for (int ks = 0; ks < 4; ks++) {
            const uint32_t kb = ks * 32;
            uint32_t af[4][4], bf[4][4];
            #pragma unroll
            for (int mt = 0; mt < 4; mt++) {
                uint32_t ad = Abase + SWZ128(a_rowoff[mt] + kb);
                LDSM_X4(af[mt][0], af[mt][1], af[mt][2], af[mt][3], ad);
            }
            #pragma unroll
            for (int np = 0; np < 4; np++) {
                uint32_t bd = Bbase + SWZ128(b_rowoff[np] + kb);
                LDSM_X4(bf[np][0], bf[np][1], bf[np][2], bf[np][3], bd);
            }
            #pragma unroll
            for (int mt = 0; mt < 4; mt++)
                #pragma unroll
                for (int nt = 0; nt < 8; nt++)
                    MMA_F16(acc[mt][nt],
                            af[mt][0], af[mt][1], af[mt][2], af[mt][3],
                            bf[nt >> 1][(nt & 1) * 2],
                            bf[nt >> 1][(nt & 1) * 2 + 1]);
        }

        MBAR_ARRIVE(EMPTY + 8 * slot);
        if (++slot == NSLOT) { slot = 0; phase ^= 1; }
    }

    // epilogue
    const int qid = lane >> 2, tg = lane & 3;
    #pragma unroll
    for (int mt = 0; mt < 4; mt++) {
        #pragma unroll
        for (int nt = 0; nt < 8; nt++) {
            int row = m0 + warp_m * 64 + mt * 16 + qid;
            int col = n0 + warp_n * 64 + nt * 8 + tg * 2;
            *(float2*)&out[(size_t)row * N_TOTAL + col] =
                make_float2(acc[mt][nt][0], acc[mt][nt][1]);
            *(float2*)&out[(size_t)(row + 8) * N_TOTAL + col] =
                make_float2(acc[mt][nt][2], acc[mt][nt][3]);
        }
    }
}

extern "C" void kernel_launch(void* const* d_in, const int* in_sizes, int n_in,
                              void* d_out, int out_size) {
    const float* x        = (const float*)d_in[0];
    const int*   base_idx = (const int*)d_in[1];
    const int*   fine_idx = (const int*)d_in[2];
    const float* scale    = (const float*)d_in[3];
    const float* lut      = (const float*)d_in[4];
    float* out = (float*)d_out;

    cudaFuncSetAttribute(ghost_dequant, cudaFuncAttributeMaxDynamicSharedMemorySize,
                         131072);
    cudaFuncSetAttribute(ghost_gemm, cudaFuncAttributeMaxDynamicSharedMemorySize,
                         SMEM_GEMM);

    ghost_dequant<<<148, 1024, 131072>>>(base_idx, fine_idx, scale, lut, x);
    dim3 grid(M_TOTAL / BM, N_TOTAL / BN);  // (4, 32), M fastest, single wave
    ghost_gemm<<<grid, THREADS, SMEM_GEMM>>>(out);
}

// round 11
// speedup vs baseline: 1.1992x; 1.1992x over previous
#include <cuda_runtime.h>
#include <cuda_fp16.h>
#include <cstdint>

// GhostLinearTandem FUSED: one GEMM kernel with inline two-level-LUT dequant.
//  prepass: x fp32->fp16 (g_xh), lut fp32->fp16 (g_lut_h). ~12MB traffic.
//  main: BM=512 (ALL of M) x BN=64 per CTA, grid 128 = single wave.
//    Index data read EXACTLY ONCE (no W scratch). LUT fp16 in smem (128KB).
//    Per stage (BK=32 halves): dequant 2048 B elems inline (regs->gather->STS),
//    A via cp.async double buffer, fp16 mma.sync m16n8k16 + ldmatrix.x4 on
//    pair-packed SW128 smem. 16 warps of 64x32 tiles. 512 threads, 1 CTA/SM.

#define M_TOTAL 512
#define N_TOTAL 8192
#define K_TOTAL 4096

__device__ __align__(16) __half g_xh[(size_t)M_TOTAL * K_TOTAL];  // 4 MiB
__device__ __align__(16) __half g_lut_h[65536];                   // 128 KiB

__device__ __forceinline__ uint32_t smem_u32(const void* p) {
    uint32_t a;
    asm("{ .reg .u64 t; cvta.to.shared.u64 t, %1; cvt.u32.u64 %0, t; }"
        : "=r"(a) : "l"(p));
    return a;
}
__device__ __forceinline__ uint32_t h2_to_u32(__half2 h) {
    uint32_t u; *(__half2*)&u = h; return u;
}
#define SWZ128(off) ((off) ^ (((off) >> 3) & 0x70))
// pair-packed rows: two 64B logical rows per 128B swizzle atom
#define PB(r, cb) ((((r) >> 1) * 128) + (((r) & 1) * 64) + (cb))

#define CP16(dst, src) \
    asm volatile("cp.async.cg.shared.global [%0], [%1], 16;" :: "r"(dst), "l"(src))
#define CP_COMMIT() asm volatile("cp.async.commit_group;")
#define CP_WAIT1()  asm volatile("cp.async.wait_group 1;")

#define LDSM_X4(r0, r1, r2, r3, addr)                                     \
    asm volatile("ldmatrix.sync.aligned.m8n8.x4.shared.b16 {%0,%1,%2,%3}, [%4];" \
                 : "=r"(r0), "=r"(r1), "=r"(r2), "=r"(r3) : "r"(addr))

#define MMA_F16(d, a0, a1, a2, a3, b0, b1)                             \
    asm volatile(                                                      \
        "mma.sync.aligned.m16n8k16.row.col.f32.f16.f16.f32 "           \
        "{%0,%1,%2,%3}, {%4,%5,%6,%7}, {%8,%9}, {%0,%1,%2,%3};\n"      \
        : "+f"((d)[0]), "+f"((d)[1]), "+f"((d)[2]), "+f"((d)[3])       \
        : "r"(a0), "r"(a1), "r"(a2), "r"(a3), "r"(b0), "r"(b1))

// ---------------------------------------------------------------- prepass
__global__ __launch_bounds__(256)
void ghost_prepass(const float* __restrict__ x, const float* __restrict__ lut) {
    int t = blockIdx.x * blockDim.x + threadIdx.x;
    int stride = gridDim.x * blockDim.x;
    const float4* xp = (const float4*)x;
    for (int g = t; g < M_TOTAL * K_TOTAL / 8; g += stride) {
        float4 u = xp[2 * g], v = xp[2 * g + 1];
        __half2 h[4] = {__floats2half2_rn(u.x, u.y), __floats2half2_rn(u.z, u.w),
                        __floats2half2_rn(v.x, v.y), __floats2half2_rn(v.z, v.w)};
        *(uint4*)&g_xh[(size_t)g * 8] = *(uint4*)h;
    }
    const float4* lp = (const float4*)lut;
    for (int g = t; g < 65536 / 8; g += stride) {
        float4 u = lp[2 * g], v = lp[2 * g + 1];
        __half2 h[4] = {__floats2half2_rn(u.x, u.y), __floats2half2_rn(u.z, u.w),
                        __floats2half2_rn(v.x, v.y), __floats2half2_rn(v.z, v.w)};
        *(uint4*)&g_lut_h[g * 8] = *(uint4*)h;
    }
}

// ---------------------------------------------------------------- fused GEMM
#define BM 512
#define BN 64
#define BKH 32                        // halves per stage (64 B per logical row)
#define NS (K_TOTAL / BKH)            // 128 stages
#define LUT_BYTES 131072
#define A_ST (BM * 64)                // 32768 B per A buffer
#define B_ST (BN * 64)                // 4096 B per B buffer
#define AOFF LUT_BYTES
#define BOFF (LUT_BYTES + 2 * A_ST)
#define SMEM_FUSED (LUT_BYTES + 2 * A_ST + 2 * B_ST)  // 204800
#define THREADS 512

__global__ __launch_bounds__(THREADS, 1)
void ghost_fused(const int* __restrict__ base_idx,
                 const int* __restrict__ fine_idx,
                 const float* __restrict__ scale,
                 float* __restrict__ out) {
    extern __shared__ char smem[];
    const uint32_t sb = smem_u32(smem);
    __half* lut_s = (__half*)smem;
    const int tid = threadIdx.x;
    const int warp = tid >> 5, lane = tid & 31;
    const int n0 = blockIdx.x * BN;

    // ---- LUT -> smem ----
    {
        const uint4* src = (const uint4*)g_lut_h;  // 8192 uint4
        uint4* dst = (uint4*)smem;
        #pragma unroll
        for (int i = 0; i < 16; i++) dst[tid + i * THREADS] = src[tid + i * THREADS];
    }

    // ---- dequant role: thread t -> B row (t>>3), 4 elems at (t&7)*4 ----
    const int drow = tid >> 3;              // 0..63
    const int dk4 = (tid & 7) * 4;          // 0,4,..28
    const float scl = scale[n0 + drow];
    const int* bsrc = base_idx + (size_t)(n0 + drow) * K_TOTAL + dk4;
    const int* fsrc = fine_idx + (size_t)(n0 + drow) * K_TOTAL + dk4;
    const uint32_t bsts = PB(drow, dk4 * 2);   // byte offset pre-swizzle

    __syncthreads();    // LUT resident

    // ---- A loader role: 4 x 16B chunks per thread per stage ----
    // chunk c: row=c>>2, ci=c&3 -> src g_xh[row*K + kh + ci*8]
    auto load_A = [&](int s, int slot) {
        const int kh = s * BKH;
        #pragma unroll
        for (int i = 0; i < 4; i++) {
            int c = tid + i * THREADS;
            int row = c >> 2, ci = c & 3;
            CP16(sb + AOFF + slot * A_ST + SWZ128(PB(row, ci * 16)),
                 g_xh + (size_t)row * K_TOTAL + kh + ci * 8);
        }
        CP_COMMIT();
    };

    // ---- warp tiling: 8 warps along M (64 rows), 2 along N (32 cols) ----
    const int warp_m = warp >> 1;
    const int warp_n = warp & 1;
    const int a_row0 = warp_m * 64 + ((lane >> 3) & 1) * 8 + (lane & 7);
    const int a_koff = (lane >> 4) * 8;            // halves
    const int b_row0 = warp_n * 32 + ((lane >> 4) & 1) * 8 + (lane & 7);
    const int b_koff = ((lane >> 3) & 1) * 8;

    float acc[4][4][4];
    #pragma unroll
    for (int mt = 0; mt < 4; mt++)
        #pragma unroll
        for (int nt = 0; nt < 4; nt++)
            #pragma unroll
            for (int r = 0; r < 4; r++) acc[mt][nt][r] = 0.0f;

    // ---- prologue: idx(0) into regs, A(0) in flight ----
    int4 rb = *(const int4*)bsrc;
    int4 rf = *(const int4*)fsrc;
    load_A(0, 0);

    for (int s = 0; s < NS; ++s) {
        const int buf = s & 1;

        // dequant stage s -> STS B[buf]
        {
            __half2 lo = __floats2half2_rn(
                __half2float(lut_s[(rb.x << 8) + rf.x]) * scl,
                __half2float(lut_s[(rb.y << 8) + rf.y]) * scl);
            __half2 hi = __floats2half2_rn(
                __half2float(lut_s[(rb.z << 8) + rf.z]) * scl,
                __half2float(lut_s[(rb.w << 8) + rf.w]) * scl);
            uint2 pk = make_uint2(h2_to_u32(lo), h2_to_u32(hi));
            *(uint2*)(smem + BOFF - LUT_BYTES + LUT_BYTES + buf * B_ST +
                      SWZ128(bsts)) = pk;   // = smem + BOFF + buf*B_ST + swz
        }

        // idx prefetch s+1
        if (s + 1 < NS) {
            rb = *(const int4*)(bsrc + (s + 1) * BKH);
            rf = *(const int4*)(fsrc + (s + 1) * BKH);
        }

        // A(s+1) cp.async (A[(s+1)&1] last read in MMA(s-1), guarded by the
        // trailing barrier of iter s-1)
        if (s + 1 < NS) load_A(s + 1, buf ^ 1);
        else CP_COMMIT();          // keep wait_group accounting exact

        CP_WAIT1();                // A(s) complete (A(s+1) may fly)
        __syncthreads();           // A[buf] + B[buf] visible to all warps

        const uint32_t Abase = sb + AOFF + buf * A_ST;
        const uint32_t Bbase = sb + BOFF + buf * B_ST;
        #pragma unroll
        for (int ks = 0; ks < 2; ks++) {
            const int kb = ks * 32;   // bytes (16 halves)
            uint32_t af[4][4], bf[2][4];
            #pragma unroll
            for (int mt = 0; mt < 4; mt++) {
                uint32_t ad = Abase +
                    SWZ128(PB(a_row0 + mt * 16, a_koff * 2 + kb));
                LDSM_X4(af[mt][0], af[mt][1], af[mt][2], af[mt][3], ad);
            }
            #pragma unroll
            for (int np = 0; np < 2; np++) {
                uint32_t bd = Bbase +
                    SWZ128(PB(b_row0 + np * 16, b_koff * 2 + kb));
                LDSM_X4(bf[np][0], bf[np][1], bf[np][2], bf[np][3], bd);
            }
            #pragma unroll
            for (int mt = 0; mt < 4; mt++)
                #pragma unroll
                for (int nt = 0; nt < 4; nt++)
                    MMA_F16(acc[mt][nt],
                            af[mt][0], af[mt][1], af[mt][2], af[mt][3],
                            bf[nt >> 1][(nt & 1) * 2],
                            bf[nt >> 1][(nt & 1) * 2 + 1]);
        }
        __syncthreads();   // all warps done with buf before iter s+1 STS/cp.async
    }

    // ---- epilogue ----
    const int qid = lane >> 2, tg = lane & 3;
    #pragma unroll
    for (int mt = 0; mt < 4; mt++) {
        #pragma unroll
        for (int nt = 0; nt < 4; nt++) {
            int row = warp_m * 64 + mt * 16 + qid;
            int col = n0 + warp_n * 32 + nt * 8 + tg * 2;
            *(float2*)&out[(size_t)row * N_TOTAL + col] =
                make_float2(acc[mt][nt][0], acc[mt][nt][1]);
            *(float2*)&out[(size_t)(row + 8) * N_TOTAL + col] =
                make_float2(acc[mt][nt][2], acc[mt][nt][3]);
        }
    }
}

extern "C" void kernel_launch(void* const* d_in, const int* in_sizes, int n_in,
                              void* d_out, int out_size) {
    const float* x        = (const float*)d_in[0];
    const int*   base_idx = (const int*)d_in[1];
    const int*   fine_idx = (const int*)d_in[2];
    const float* scale    = (const float*)d_in[3];
    const float* lut      = (const float*)d_in[4];
    float* out = (float*)d_out;

    cudaFuncSetAttribute(ghost_fused, cudaFuncAttributeMaxDynamicSharedMemorySize,
                         SMEM_FUSED);

    ghost_prepass<<<296, 256>>>(x, lut);
    ghost_fused<<<N_TOTAL / BN, THREADS, SMEM_FUSED>>>(base_idx, fine_idx,
                                                       scale, out);
}